// round 9
// baseline (speedup 1.0000x reference)
#include <cuda_runtime.h>
#include <cstdint>

// ---------------- problem dims ----------------
static constexpr int N_ROWS = 8192;    // samples
static constexpr int C_CLS  = 1000;    // classes
static constexpr int D_DIM  = 10000;   // hypervector dim
static constexpr int D_PAD  = 10240;   // padded: 160 * 64 (zeros contribute 0 to dot)
static constexpr int C_PAD  = 1024;    // padded classes (rows >= 1000 are zero)

// ---------------- GEMM tiling (bf16) ----------------
static constexpr int BM = 64;
static constexpr int BN = 128;
static constexpr int BK = 64;               // 64 bf16 = 128B rows
static constexpr int KT = D_PAD / BK;       // 160 K-iterations
static constexpr int STAGES = 3;

static constexpr int A_BYTES = BM * BK * 2;            // 8192
static constexpr int STAGE_BYTES = (BM + BN) * BK * 2; // 24576
static constexpr int SMEM_TOTAL = STAGES * STAGE_BYTES; // 73728 -> 3 CTAs/SM

// ---------------- scratch (device globals; no allocation allowed) ----------
__device__ uint16_t g_B[(size_t)C_PAD * D_PAD];   // 21 MB bf16, holds 1-2*B
__device__ int g_csum[C_PAD];

// ---------------- helpers ----------------
__device__ __forceinline__ uint32_t smem_to_u32(const void* p) {
    uint32_t a;
    asm("{ .reg .u64 t; cvta.to.shared.u64 t, %1; cvt.u32.u64 %0, t; }" : "=r"(a) : "l"(p));
    return a;
}

__device__ __forceinline__ void cp_async16(uint32_t smem_addr, const void* gptr) {
    asm volatile("cp.async.cg.shared.global [%0], [%1], 16;"
                 :: "r"(smem_addr), "l"(gptr) : "memory");
}
#define CP_COMMIT() asm volatile("cp.async.commit_group;" ::: "memory")
#define CP_WAIT1()  asm volatile("cp.async.wait_group 1;" ::: "memory")

#define LDSM_X4(r0, r1, r2, r3, addr) \
    asm volatile("ldmatrix.sync.aligned.m8n8.x4.shared.b16 {%0,%1,%2,%3}, [%4];" \
                 : "=r"(r0), "=r"(r1), "=r"(r2), "=r"(r3) : "r"(addr))

// bf16 MMA, fp32 accumulate: D += A(16x16) * B(16x8)^T
#define MMA_BF16(d, a, b) \
    asm volatile("mma.sync.aligned.m16n8k16.row.col.f32.bf16.bf16.f32 " \
                 "{%0,%1,%2,%3}, {%4,%5,%6,%7}, {%8,%9}, {%0,%1,%2,%3};" \
                 : "+f"((d)[0]), "+f"((d)[1]), "+f"((d)[2]), "+f"((d)[3]) \
                 : "r"((a)[0]), "r"((a)[1]), "r"((a)[2]), "r"((a)[3]), \
                   "r"((b)[0]), "r"((b)[1]))

// pack two floats into one u32 holding two bf16 (exact for small ints / {0,1})
__device__ __forceinline__ uint32_t packbf2(float lo, float hi) {
    return __byte_perm(__float_as_uint(lo), __float_as_uint(hi), 0x7632);
}

// ---------------- conversion: B {0,1} -> bf16(1-2B) in {-1,+1}, + csum ----
__global__ void __launch_bounds__(256) cvt_b_kernel(const float* __restrict__ src) {
    const int row = blockIdx.x;       // 0..1023
    const int tid = threadIdx.x;
    int acc = 0;
    uint4* d4 = reinterpret_cast<uint4*>(g_B + (size_t)row * D_PAD);  // 16B = 8 bf16
    if (row < C_CLS) {
        const float4* s4 = reinterpret_cast<const float4*>(src + (size_t)row * D_DIM);
        for (int i = tid; i < D_PAD / 8; i += 256) {
            uint4 o;
            if (i < D_DIM / 8) {
                float4 v0 = s4[i * 2 + 0];
                float4 v1 = s4[i * 2 + 1];
                float fs = v0.x + v0.y + v0.z + v0.w + v1.x + v1.y + v1.z + v1.w;
                acc += (int)fs;   // csum: exact
                o.x = packbf2(1.0f - 2.0f * v0.x, 1.0f - 2.0f * v0.y);
                o.y = packbf2(1.0f - 2.0f * v0.z, 1.0f - 2.0f * v0.w);
                o.z = packbf2(1.0f - 2.0f * v1.x, 1.0f - 2.0f * v1.y);
                o.w = packbf2(1.0f - 2.0f * v1.z, 1.0f - 2.0f * v1.w);
            } else { o.x = 0u; o.y = 0u; o.z = 0u; o.w = 0u; }  // pad MUST be 0
            d4[i] = o;
        }
    } else {
        uint4 z; z.x = 0u; z.y = 0u; z.z = 0u; z.w = 0u;
        for (int i = tid; i < D_PAD / 8; i += 256) d4[i] = z;
    }
    __shared__ int red[8];
    for (int off = 16; off > 0; off >>= 1) acc += __shfl_xor_sync(0xffffffffu, acc, off);
    if ((tid & 31) == 0) red[tid >> 5] = acc;
    __syncthreads();
    if (tid < 8) {
        int v = red[tid];
        for (int off = 4; off > 0; off >>= 1) v += __shfl_xor_sync(0xffu, v, off);
        if (tid == 0) g_csum[row] = v;
    }
}

// ---------------- GEMM: dist = csum[c] + A(fp32,{0,1}) . B'(bf16,{-1,1}) ----
// Block tile 64x128, 256 threads = 8 warps 2(M) x 4(N), warp tile 32x32.
// A is read as fp32 from the harness input and converted in-register.
__global__ void __launch_bounds__(256, 3) hd_gemm_kernel(
        const float* __restrict__ aSrc, float* __restrict__ out) {
    extern __shared__ char smem[];
    const uint32_t smem_base = smem_to_u32(smem);
    const int tid = threadIdx.x;
    const int wid = tid >> 5;
    const int lane = tid & 31;
    const int wm = wid & 1;     // 0..1  (M)
    const int wn = wid >> 1;    // 0..3  (N)
    const int colTile = blockIdx.x;   // 0..7
    const int rowTile = blockIdx.y;   // 0..127

    const uint16_t* bG = g_B + (size_t)colTile * BN * D_PAD;

    // ---- A loader: thread -> (row r, quarter q). 64 rows x 64 fp32 per stage.
    const int ar = tid >> 2;          // 0..63
    const int aq = tid & 3;           // 0..3 : fp32 cols [16*aq, 16*aq+16)
    const float* aRow = aSrc + (size_t)(rowTile * BM + ar) * D_DIM;
    const int aXr = ar & 7;
    const uint32_t aRowBase = (uint32_t)(ar * 128);

    // ---- B loader: cp.async, 4 x 16B per thread
    const int blr = tid >> 3;  // 0..31
    const int blc = tid & 7;   // 16B chunk

    auto ldgA = [&](int kt, int half, float4* av) {
        const int cbase = kt * BK + aq * 16 + half * 8;
#pragma unroll
        for (int j = 0; j < 2; ++j) {
            const int col = cbase + 4 * j;
            if (col < D_DIM) av[j] = *reinterpret_cast<const float4*>(aRow + col);
            else { av[j].x = 0.f; av[j].y = 0.f; av[j].z = 0.f; av[j].w = 0.f; }
        }
    };
    auto stsA = [&](int s, int half, const float4* av) {
        // 8 fp32 -> one 16B bf16 chunk; chunk index = 2*aq + half
        const int ch = (2 * aq + half) ^ aXr;
        uint4 o;
        o.x = packbf2(av[0].x, av[0].y);
        o.y = packbf2(av[0].z, av[0].w);
        o.z = packbf2(av[1].x, av[1].y);
        o.w = packbf2(av[1].z, av[1].w);
        *reinterpret_cast<uint4*>(smem + s * STAGE_BYTES + aRowBase + ch * 16) = o;
    };
    auto cpB = [&](int kt, int s) {
        const uint32_t stBase = smem_base + s * STAGE_BYTES + A_BYTES;
        const size_t gchunk = (size_t)kt * 8 + blc;
#pragma unroll
        for (int i = 0; i < 4; ++i) {
            const int r = blr + 32 * i;           // 0..127
            const uint32_t off = (uint32_t)(r * 128 + ((blc ^ (r & 7)) << 4));
            cp_async16(stBase + off,
                       reinterpret_cast<const char*>(bG) + ((size_t)r * 1280 + gchunk) * 16);
        }
    };

    // ldmatrix lane addressing (validated R3 scheme)
    const int aLane16 = lane & 15;
    const int aTop = lane >> 4;
    uint32_t aRowOff[2]; int aXor[2];
#pragma unroll
    for (int mt = 0; mt < 2; ++mt) {
        const int r = wm * 32 + mt * 16 + aLane16;      // A rows 0..63
        aRowOff[mt] = (uint32_t)(r * 128);
        aXor[mt] = r & 7;
    }
    const int bRowInTile = ((lane & 16) >> 1) + (lane & 7);
    const int bTop = (lane >> 3) & 1;
    uint32_t bRowOff[2]; int bXor[2];
#pragma unroll
    for (int p = 0; p < 2; ++p) {
        const int r = wn * 32 + p * 16 + bRowInTile;    // B rows 0..127
        bRowOff[p] = (uint32_t)(r * 128);
        bXor[p] = r & 7;
    }

    float acc[2][4][4];
#pragma unroll
    for (int mt = 0; mt < 2; ++mt)
#pragma unroll
        for (int nt = 0; nt < 4; ++nt)
#pragma unroll
            for (int q = 0; q < 4; ++q) acc[mt][nt][q] = 0.0f;

    // prologue: stages 0,1
    {
        float4 av[2];
#pragma unroll
        for (int p = 0; p < 2; ++p) {
            ldgA(p, 0, av); stsA(p, 0, av);
            ldgA(p, 1, av); stsA(p, 1, av);
            cpB(p, p);
            CP_COMMIT();
        }
    }

    for (int kt = 0; kt < KT; ++kt) {
        const int sNext = (kt + 2) % STAGES;
        const bool pre = (kt + 2) < KT;
        float4 av[2];
        if (pre) ldgA(kt + 2, 0, av);   // issue early, consumed mid-loop

        CP_WAIT1();
        __syncthreads();

        const uint32_t aBase = smem_base + (kt % STAGES) * STAGE_BYTES;
        const uint32_t bBase = aBase + A_BYTES;
#pragma unroll
        for (int ks = 0; ks < 4; ++ks) {     // 4 x k16 within BK=64
            uint32_t af[2][4];
#pragma unroll
            for (int mt = 0; mt < 2; ++mt) {
                const int chunk = ks * 2 + aTop;
                const uint32_t addr = aBase + aRowOff[mt] + (uint32_t)((chunk ^ aXor[mt]) << 4);
                LDSM_X4(af[mt][0], af[mt][1], af[mt][2], af[mt][3], addr);
            }
            uint32_t bf[4][2];
#pragma unroll
            for (int p = 0; p < 2; ++p) {
                const int chunk = ks * 2 + bTop;
                const uint32_t addr = bBase + bRowOff[p] + (uint32_t)((chunk ^ bXor[p]) << 4);
                LDSM_X4(bf[2 * p][0], bf[2 * p][1], bf[2 * p + 1][0], bf[2 * p + 1][1], addr);
            }
#pragma unroll
            for (int mt = 0; mt < 2; ++mt)
#pragma unroll
                for (int nt = 0; nt < 4; ++nt)
                    MMA_BF16(acc[mt][nt], af[mt], bf[nt]);

            if (ks == 1 && pre) {        // mid-loop: store half0, fetch half1
                stsA(sNext, 0, av);
                ldgA(kt + 2, 1, av);
            }
        }
        if (pre) {
            stsA(sNext, 1, av);
            cpB(kt + 2, sNext);
        }
        CP_COMMIT();
    }

    // ---------------- epilogue: dist = csum + dot(A, 1-2B) (exact) ----
    const int groupID = lane >> 2;   // 0..7
    const int tig = lane & 3;        // 0..3
#pragma unroll
    for (int mt = 0; mt < 2; ++mt) {
        const int m0 = rowTile * BM + wm * 32 + mt * 16 + groupID;
        float* orow0 = out + (size_t)m0 * C_CLS;
        float* orow1 = out + (size_t)(m0 + 8) * C_CLS;
#pragma unroll
        for (int nt = 0; nt < 4; ++nt) {
            const int c0 = colTile * BN + wn * 32 + nt * 8 + 2 * tig;
            if (c0 < C_CLS) {   // C_CLS even; pair fully valid
                const float cs0 = (float)g_csum[c0];
                const float cs1 = (float)g_csum[c0 + 1];
                float2 v0, v1;
                v0.x = cs0 + acc[mt][nt][0];
                v0.y = cs1 + acc[mt][nt][1];
                v1.x = cs0 + acc[mt][nt][2];
                v1.y = cs1 + acc[mt][nt][3];
                *reinterpret_cast<float2*>(orow0 + c0) = v0;
                *reinterpret_cast<float2*>(orow1 + c0) = v1;
            }
        }
    }
}

// ---------------- launch ----------------
extern "C" void kernel_launch(void* const* d_in, const int* in_sizes, int n_in,
                              void* d_out, int out_size) {
    const float* samples = (const float*)d_in[0];   // [8192, 10000]
    const float* classes = (const float*)d_in[1];   // [1000, 10000]
    float* out = (float*)d_out;                     // [8192, 1000]

    cudaFuncSetAttribute(hd_gemm_kernel, cudaFuncAttributeMaxDynamicSharedMemorySize,
                         SMEM_TOTAL);

    cvt_b_kernel<<<C_PAD, 256>>>(classes);

    dim3 grid(C_PAD / BN, N_ROWS / BM);  // (8, 128) = 1024 tiles
    hd_gemm_kernel<<<grid, 256, SMEM_TOTAL>>>(samples, out);
}

// round 10
// speedup vs baseline: 1.7248x; 1.7248x over previous
#include <cuda_runtime.h>
#include <cstdint>

// ---------------- problem dims ----------------
static constexpr int N_ROWS = 8192;    // samples
static constexpr int C_CLS  = 1000;    // classes
static constexpr int D_DIM  = 10000;   // hypervector dim
static constexpr int D_PAD  = 10240;   // padded: 160 * 64 (zeros contribute 0 to dot)
static constexpr int C_PAD  = 1024;    // padded classes (rows >= 1000 are zero)

// ---------------- GEMM tiling (bf16) ----------------
static constexpr int BM = 64;
static constexpr int BN = 128;
static constexpr int BK = 64;               // 64 bf16 = 128B rows
static constexpr int KT = D_PAD / BK;       // 160 K-iterations
static constexpr int STAGES = 3;

static constexpr int A_BYTES = BM * BK * 2;            // 8192
static constexpr int STAGE_BYTES = (BM + BN) * BK * 2; // 24576
static constexpr int SMEM_TOTAL = STAGES * STAGE_BYTES; // 73728 -> 3 CTAs/SM

// ---------------- scratch (device globals; no allocation allowed) ----------
__device__ uint16_t g_A[(size_t)N_ROWS * D_PAD];   // 168 MB bf16 {0,1}
__device__ uint16_t g_B[(size_t)C_PAD  * D_PAD];   // 21 MB bf16, holds 1-2*B
__device__ int g_csum[C_PAD];

// ---------------- helpers ----------------
__device__ __forceinline__ uint32_t smem_to_u32(const void* p) {
    uint32_t a;
    asm("{ .reg .u64 t; cvta.to.shared.u64 t, %1; cvt.u32.u64 %0, t; }" : "=r"(a) : "l"(p));
    return a;
}

__device__ __forceinline__ void cp_async16(uint32_t smem_addr, const void* gptr) {
    asm volatile("cp.async.cg.shared.global [%0], [%1], 16;"
                 :: "r"(smem_addr), "l"(gptr) : "memory");
}
#define CP_COMMIT() asm volatile("cp.async.commit_group;" ::: "memory")
#define CP_WAIT1()  asm volatile("cp.async.wait_group 1;" ::: "memory")

#define LDSM_X4(r0, r1, r2, r3, addr) \
    asm volatile("ldmatrix.sync.aligned.m8n8.x4.shared.b16 {%0,%1,%2,%3}, [%4];" \
                 : "=r"(r0), "=r"(r1), "=r"(r2), "=r"(r3) : "r"(addr))

// bf16 MMA, fp32 accumulate: D += A(16x16) * B(16x8)^T
#define MMA_BF16(d, a, b) \
    asm volatile("mma.sync.aligned.m16n8k16.row.col.f32.bf16.bf16.f32 " \
                 "{%0,%1,%2,%3}, {%4,%5,%6,%7}, {%8,%9}, {%0,%1,%2,%3};" \
                 : "+f"((d)[0]), "+f"((d)[1]), "+f"((d)[2]), "+f"((d)[3]) \
                 : "r"((a)[0]), "r"((a)[1]), "r"((a)[2]), "r"((a)[3]), \
                   "r"((b)[0]), "r"((b)[1]))

// pack two floats into one u32 holding two bf16 (exact for {-1,0,1})
__device__ __forceinline__ uint32_t packbf2(float lo, float hi) {
    return __byte_perm(__float_as_uint(lo), __float_as_uint(hi), 0x7632);
}

// ---------------- conversion A: fp32 {0,1} -> bf16 ----
__global__ void __launch_bounds__(256) cvt_a_kernel(const float* __restrict__ src) {
    const int row = blockIdx.x;       // 0..8191
    const int tid = threadIdx.x;
    uint4* d4 = reinterpret_cast<uint4*>(g_A + (size_t)row * D_PAD);  // 16B = 8 bf16
    const float4* s4 = reinterpret_cast<const float4*>(src + (size_t)row * D_DIM);
    for (int i = tid; i < D_PAD / 8; i += 256) {
        uint4 o;
        if (i < D_DIM / 8) {
            float4 v0 = s4[i * 2 + 0];
            float4 v1 = s4[i * 2 + 1];
            o.x = packbf2(v0.x, v0.y);
            o.y = packbf2(v0.z, v0.w);
            o.z = packbf2(v1.x, v1.y);
            o.w = packbf2(v1.z, v1.w);
        } else { o.x = 0u; o.y = 0u; o.z = 0u; o.w = 0u; }
        d4[i] = o;
    }
}

// ---------------- conversion B: {0,1} -> bf16(1-2B) in {-1,+1}, + csum ----
__global__ void __launch_bounds__(256) cvt_b_kernel(const float* __restrict__ src) {
    const int row = blockIdx.x;       // 0..1023
    const int tid = threadIdx.x;
    int acc = 0;
    uint4* d4 = reinterpret_cast<uint4*>(g_B + (size_t)row * D_PAD);
    if (row < C_CLS) {
        const float4* s4 = reinterpret_cast<const float4*>(src + (size_t)row * D_DIM);
        for (int i = tid; i < D_PAD / 8; i += 256) {
            uint4 o;
            if (i < D_DIM / 8) {
                float4 v0 = s4[i * 2 + 0];
                float4 v1 = s4[i * 2 + 1];
                float fs = v0.x + v0.y + v0.z + v0.w + v1.x + v1.y + v1.z + v1.w;
                acc += (int)fs;   // csum: exact
                o.x = packbf2(1.0f - 2.0f * v0.x, 1.0f - 2.0f * v0.y);
                o.y = packbf2(1.0f - 2.0f * v0.z, 1.0f - 2.0f * v0.w);
                o.z = packbf2(1.0f - 2.0f * v1.x, 1.0f - 2.0f * v1.y);
                o.w = packbf2(1.0f - 2.0f * v1.z, 1.0f - 2.0f * v1.w);
            } else { o.x = 0u; o.y = 0u; o.z = 0u; o.w = 0u; }  // pad MUST be 0
            d4[i] = o;
        }
    } else {
        uint4 z; z.x = 0u; z.y = 0u; z.z = 0u; z.w = 0u;
        for (int i = tid; i < D_PAD / 8; i += 256) d4[i] = z;
    }
    __shared__ int red[8];
    for (int off = 16; off > 0; off >>= 1) acc += __shfl_xor_sync(0xffffffffu, acc, off);
    if ((tid & 31) == 0) red[tid >> 5] = acc;
    __syncthreads();
    if (tid < 8) {
        int v = red[tid];
        for (int off = 4; off > 0; off >>= 1) v += __shfl_xor_sync(0xffu, v, off);
        if (tid == 0) g_csum[row] = v;
    }
}

// ---------------- bf16 GEMM + fused Hamming epilogue ----------------
// Block tile 64x128, 128 threads = 4 warps arranged 2 (M) x 2 (N);
// warp tile 32x64 -> 25% less smem crossbar traffic than 32x32.
// dist = csum[c] + dot(A{0,1}, B'{-1,+1}).  3 CTAs/SM, 1024 tiles.
__global__ void __launch_bounds__(128, 3) hd_gemm_kernel(float* __restrict__ out) {
    extern __shared__ char smem[];
    const uint32_t smem_base = smem_to_u32(smem);
    const int tid = threadIdx.x;
    const int wid = tid >> 5;
    const int lane = tid & 31;
    const int wm = wid & 1;     // 0..1  (M: 32 rows each)
    const int wn = wid >> 1;    // 0..1  (N: 64 cols each)
    const int colTile = blockIdx.x;   // 0..7
    const int rowTile = blockIdx.y;   // 0..127

    const uint16_t* aG = g_A + (size_t)rowTile * BM * D_PAD;
    const uint16_t* bG = g_B + (size_t)colTile * BN * D_PAD;

    // loader: 128 threads x 12 iters x 16B. smem rows 0..63 = A, 64..191 = B.
    const int lr = tid >> 3;   // base row 0..15 (stride 16)
    const int lc = tid & 7;    // 16B chunk 0..7 within 128B row

    auto load_stage = [&](int kt, int s) {
        const uint32_t stBase = smem_base + s * STAGE_BYTES;
        const size_t gchunk = (size_t)kt * 8 + lc;   // 16B chunks; row = 1280 chunks
#pragma unroll
        for (int i = 0; i < 12; ++i) {
            const int r = lr + 16 * i;               // 0..191
            const uint32_t off = (uint32_t)(r * 128 + ((lc ^ (r & 7)) << 4));
            const char* src = (r < 64)
                ? reinterpret_cast<const char*>(aG) + ((size_t)r * 1280 + gchunk) * 16
                : reinterpret_cast<const char*>(bG) + ((size_t)(r - 64) * 1280 + gchunk) * 16;
            cp_async16(stBase + off, src);
        }
    };

    // ldmatrix lane addressing (validated R3 scheme)
    const int aLane16 = lane & 15;
    const int aTop = lane >> 4;              // chunk offset 0/1 within the 32B k16
    uint32_t aRowOff[2]; int aXor[2];
#pragma unroll
    for (int mt = 0; mt < 2; ++mt) {
        const int r = wm * 32 + mt * 16 + aLane16;      // A rows 0..63
        aRowOff[mt] = (uint32_t)(r * 128);
        aXor[mt] = r & 7;
    }
    const int bRowInTile = ((lane & 16) >> 1) + (lane & 7);  // +8 for lanes>=16
    const int bTop = (lane >> 3) & 1;        // chunk offset 0/1
    uint32_t bRowOff[4]; int bXor[4];
#pragma unroll
    for (int p = 0; p < 4; ++p) {
        const int r = wn * 64 + p * 16 + bRowInTile;    // B rows 0..127
        bRowOff[p] = (uint32_t)(r * 128);
        bXor[p] = r & 7;
    }

    float acc[2][8][4];
#pragma unroll
    for (int mt = 0; mt < 2; ++mt)
#pragma unroll
        for (int nt = 0; nt < 8; ++nt)
#pragma unroll
            for (int q = 0; q < 4; ++q) acc[mt][nt][q] = 0.0f;

    // prologue: 2 stages in flight
    load_stage(0, 0); CP_COMMIT();
    load_stage(1, 1); CP_COMMIT();

    for (int kt = 0; kt < KT; ++kt) {
        CP_WAIT1();
        __syncthreads();
        if (kt + 2 < KT) load_stage(kt + 2, (kt + 2) % STAGES);
        CP_COMMIT();

        const uint32_t aBase = smem_base + (kt % STAGES) * STAGE_BYTES;
        const uint32_t bBase = aBase + A_BYTES;
#pragma unroll
        for (int ks = 0; ks < 4; ++ks) {     // 4 x k16 within BK=64
            uint32_t af[2][4];
#pragma unroll
            for (int mt = 0; mt < 2; ++mt) {
                const int chunk = ks * 2 + aTop;
                const uint32_t addr = aBase + aRowOff[mt] + (uint32_t)((chunk ^ aXor[mt]) << 4);
                LDSM_X4(af[mt][0], af[mt][1], af[mt][2], af[mt][3], addr);
            }
            uint32_t bf[8][2];
#pragma unroll
            for (int p = 0; p < 4; ++p) {
                const int chunk = ks * 2 + bTop;
                const uint32_t addr = bBase + bRowOff[p] + (uint32_t)((chunk ^ bXor[p]) << 4);
                LDSM_X4(bf[2 * p][0], bf[2 * p][1], bf[2 * p + 1][0], bf[2 * p + 1][1], addr);
            }
#pragma unroll
            for (int mt = 0; mt < 2; ++mt)
#pragma unroll
                for (int nt = 0; nt < 8; ++nt)
                    MMA_BF16(acc[mt][nt], af[mt], bf[nt]);
        }
    }

    // ---------------- epilogue: dist = csum + dot (exact) ----
    const int groupID = lane >> 2;   // 0..7
    const int tig = lane & 3;        // 0..3
#pragma unroll
    for (int mt = 0; mt < 2; ++mt) {
        const int m0 = rowTile * BM + wm * 32 + mt * 16 + groupID;
        float* orow0 = out + (size_t)m0 * C_CLS;
        float* orow1 = out + (size_t)(m0 + 8) * C_CLS;
#pragma unroll
        for (int nt = 0; nt < 8; ++nt) {
            const int c0 = colTile * BN + wn * 64 + nt * 8 + 2 * tig;
            if (c0 < C_CLS) {   // C_CLS even; pair fully valid
                const float cs0 = (float)g_csum[c0];
                const float cs1 = (float)g_csum[c0 + 1];
                float2 v0, v1;
                v0.x = cs0 + acc[mt][nt][0];
                v0.y = cs1 + acc[mt][nt][1];
                v1.x = cs0 + acc[mt][nt][2];
                v1.y = cs1 + acc[mt][nt][3];
                *reinterpret_cast<float2*>(orow0 + c0) = v0;
                *reinterpret_cast<float2*>(orow1 + c0) = v1;
            }
        }
    }
}

// ---------------- launch ----------------
extern "C" void kernel_launch(void* const* d_in, const int* in_sizes, int n_in,
                              void* d_out, int out_size) {
    const float* samples = (const float*)d_in[0];   // [8192, 10000]
    const float* classes = (const float*)d_in[1];   // [1000, 10000]
    float* out = (float*)d_out;                     // [8192, 1000]

    cudaFuncSetAttribute(hd_gemm_kernel, cudaFuncAttributeMaxDynamicSharedMemorySize,
                         SMEM_TOTAL);

    cvt_b_kernel<<<C_PAD, 256>>>(classes);
    cvt_a_kernel<<<N_ROWS, 256>>>(samples);

    dim3 grid(C_PAD / BN, N_ROWS / BM);  // (8, 128) = 1024 tiles
    hd_gemm_kernel<<<grid, 128, SMEM_TOTAL>>>(out);
}